// round 3
// baseline (speedup 1.0000x reference)
#include <cuda_runtime.h>
#include <math.h>

// Problem constants
#define B 32
#define S 2048
#define D 1024
#define MASK_PENALTY 100000000.0f

// Tiling
#define NSPLIT 8
#define WARPS 8
#define THREADS (WARPS * 32)
#define ROWS_PER_SPLIT (S / NSPLIT)             // 256
#define ROWS_PER_WARP (ROWS_PER_SPLIT / WARPS)  // 32 (== warp size, used for mask preload)

typedef unsigned long long ull;

// Scratch (allocation-free: __device__ globals, zero-init)
__device__ float g_m[B * NSPLIT];
__device__ float g_l[B * NSPLIT];
__device__ __align__(16) float g_acc[(size_t)B * NSPLIT * D];  // 1 MB
__device__ int g_cnt[B];  // zero-initialized; self-resetting per launch

// ---- packed f32x2 helpers (Blackwell) ----
__device__ __forceinline__ ull pk2(float lo, float hi) {
    ull r; asm("mov.b64 %0, {%1,%2};" : "=l"(r) : "f"(lo), "f"(hi)); return r;
}
__device__ __forceinline__ void upk2(ull v, float& lo, float& hi) {
    asm("mov.b64 {%0,%1}, %2;" : "=f"(lo), "=f"(hi) : "l"(v));
}
__device__ __forceinline__ ull fma2(ull a, ull b, ull c) {
    ull d; asm("fma.rn.f32x2 %0, %1, %2, %3;" : "=l"(d) : "l"(a), "l"(b), "l"(c)); return d;
}
__device__ __forceinline__ ull mul2(ull a, ull b) {
    ull d; asm("mul.rn.f32x2 %0, %1, %2;" : "=l"(d) : "l"(a), "l"(b)); return d;
}
__device__ __forceinline__ ull add2(ull a, ull b) {
    ull d; asm("add.rn.f32x2 %0, %1, %2;" : "=l"(d) : "l"(a), "l"(b)); return d;
}

// ---------------------------------------------------------------------------
// Fused single-pass online-softmax attention + split merge.
// One warp per context row; each lane owns 32 of 1024 D-elements as 8x16B
// (offset 16B*(lane + 32*i), fully coalesced), held packed as f32x2 pairs.
// 8 warp partials merge in smem -> 1 partial per CTA -> last CTA per batch
// (atomic counter) merges the 8 split partials and writes the output.
// ---------------------------------------------------------------------------
__global__ void __launch_bounds__(THREADS)
attn_fused(const float* __restrict__ target,
           const float* __restrict__ context,
           const float* __restrict__ mask,
           float* __restrict__ out)
{
    const int b     = blockIdx.x;
    const int split = blockIdx.y;
    const int w     = threadIdx.x >> 5;
    const int lane  = threadIdx.x & 31;

    // Lane's slice of the query vector, packed
    const ulonglong2* tg = (const ulonglong2*)(target + (size_t)b * D);
    ull t2[16];
#pragma unroll
    for (int i = 0; i < 8; i++) {
        ulonglong2 v = tg[lane + 32 * i];
        t2[2 * i] = v.x; t2[2 * i + 1] = v.y;
    }

    ull acc2[16];
#pragma unroll
    for (int i = 0; i < 16; i++) acc2[i] = 0ull;  // {0.f, 0.f}

    float m = -INFINITY;
    float l = 0.f;

    const int s0 = split * ROWS_PER_SPLIT + w * ROWS_PER_WARP;
    const float* cb = context + (size_t)b * S * D;

    // Preload this warp's 32 masks (one per lane), broadcast per row via shfl
    const float mkv = mask[(size_t)b * S + s0 + lane];

    for (int r = 0; r < ROWS_PER_WARP; r++) {
        const ulonglong2* row = (const ulonglong2*)(cb + (size_t)(s0 + r) * D);

        ull c2[16];
#pragma unroll
        for (int i = 0; i < 8; i++) {
            ulonglong2 v = row[lane + 32 * i];
            c2[2 * i] = v.x; c2[2 * i + 1] = v.y;
        }

        // packed dot product (two chains to halve dependency depth)
        ull d0 = 0ull, d1 = 0ull;
#pragma unroll
        for (int i = 0; i < 8; i++) {
            d0 = fma2(c2[2 * i],     t2[2 * i],     d0);
            d1 = fma2(c2[2 * i + 1], t2[2 * i + 1], d1);
        }
        float a0, a1, a2, a3;
        upk2(d0, a0, a1); upk2(d1, a2, a3);
        float dot = (a0 + a1) + (a2 + a3);
#pragma unroll
        for (int off = 16; off > 0; off >>= 1)
            dot += __shfl_xor_sync(0xffffffffu, dot, off);

        const float mval = __shfl_sync(0xffffffffu, mkv, r);
        const float score = dot + (mval - 1.f) * MASK_PENALTY;

        // lazy-rescale online softmax (rescale branch is warp-uniform & rare)
        if (score > m) {
            const float sc = __expf(m - score);   // 0 on first iteration
            const ull sc2 = pk2(sc, sc);
            l *= sc;
#pragma unroll
            for (int i = 0; i < 16; i++) acc2[i] = mul2(acc2[i], sc2);
            m = score;
        }
        const float wgt = __expf(score - m);
        l += wgt;
        const ull w2 = pk2(wgt, wgt);
#pragma unroll
        for (int i = 0; i < 16; i++) acc2[i] = fma2(w2, c2[i], acc2[i]);
    }

    // ---- In-CTA merge of the 8 warp partials ----
    __shared__ float sm[WARPS];
    __shared__ float sl[WARPS];
    __shared__ __align__(16) ull sacc[WARPS][D / 2];   // 32 KB

    if (lane == 0) { sm[w] = m; sl[w] = l; }
    __syncthreads();

    float Mcta = -INFINITY;
#pragma unroll
    for (int i = 0; i < WARPS; i++) Mcta = fmaxf(Mcta, sm[i]);

    const float f = __expf(m - Mcta);
    const ull f2 = pk2(f, f);
#pragma unroll
    for (int i = 0; i < 8; i++) {
        ulonglong2 v;
        v.x = mul2(acc2[2 * i], f2);
        v.y = mul2(acc2[2 * i + 1], f2);
        ((ulonglong2*)sacc[w])[lane + 32 * i] = v;
    }
    __syncthreads();

    // 256 threads sum across the 8 warps and write the CTA partial
    const int pidx = b * NSPLIT + split;
    const int d2 = threadIdx.x;  // 0..255, one ulonglong2 (4 floats) each
    ulonglong2 sum = ((const ulonglong2*)sacc[0])[d2];
#pragma unroll
    for (int i = 1; i < WARPS; i++) {
        const ulonglong2 v = ((const ulonglong2*)sacc[i])[d2];
        sum.x = add2(sum.x, v.x);
        sum.y = add2(sum.y, v.y);
    }
    ((ulonglong2*)(g_acc + (size_t)pidx * D))[d2] = sum;

    if (threadIdx.x == 0) {
        float L = 0.f;
#pragma unroll
        for (int i = 0; i < WARPS; i++)
            L += __expf(sm[i] - Mcta) * sl[i];
        g_m[pidx] = Mcta;
        g_l[pidx] = L;
    }

    // ---- Last CTA per batch merges the NSPLIT partials ----
    __threadfence();
    __syncthreads();
    __shared__ int isLast;
    if (threadIdx.x == 0)
        isLast = (atomicAdd(&g_cnt[b], 1) == NSPLIT - 1);
    __syncthreads();
    if (!isLast) return;
    __threadfence();  // acquire

    float pm[NSPLIT], pl[NSPLIT];
#pragma unroll
    for (int p = 0; p < NSPLIT; p++) {
        pm[p] = __ldcg(&g_m[b * NSPLIT + p]);
        pl[p] = __ldcg(&g_l[b * NSPLIT + p]);
    }
    float M = -INFINITY;
#pragma unroll
    for (int p = 0; p < NSPLIT; p++) M = fmaxf(M, pm[p]);
    float L = 0.f;
#pragma unroll
    for (int p = 0; p < NSPLIT; p++) L += __expf(pm[p] - M) * pl[p];
    const float Linv = 1.f / L;

    ulonglong2 a; a.x = 0ull; a.y = 0ull;
#pragma unroll
    for (int p = 0; p < NSPLIT; p++) {
        const float fp = __expf(pm[p] - M);
        const ull fp2 = pk2(fp, fp);
        const ulonglong2 v =
            __ldcg((const ulonglong2*)(g_acc + (size_t)(b * NSPLIT + p) * D) + d2);
        a.x = fma2(fp2, v.x, a.x);
        a.y = fma2(fp2, v.y, a.y);
    }
    const ull li2 = pk2(Linv, Linv);
    a.x = mul2(a.x, li2);
    a.y = mul2(a.y, li2);
    ((ulonglong2*)(out + (size_t)b * D))[d2] = a;

    // reset counter for next (graph-replayed) launch
    if (threadIdx.x == 0) atomicExch(&g_cnt[b], 0);
}

extern "C" void kernel_launch(void* const* d_in, const int* in_sizes, int n_in,
                              void* d_out, int out_size)
{
    const float* target  = (const float*)d_in[0];  // [B, D]
    const float* context = (const float*)d_in[1];  // [B, S, D]
    const float* mask    = (const float*)d_in[2];  // [B, S]
    float* out = (float*)d_out;                    // [B, D]

    dim3 grid(B, NSPLIT);
    attn_fused<<<grid, THREADS>>>(target, context, mask, out);
}